// round 5
// baseline (speedup 1.0000x reference)
#include <cuda_runtime.h>
#include <cuda_fp16.h>
#include <cstdint>

// ===========================================================================
// GaussProjDrop: x[16384,1024] f32; per-row perm a_r(i) = (perm[i]*m_r) & 1023,
// m_r = (6*randint*r + 1) & 1023 (odd -> bijection since n = 2^10).
//   y = gather(x) @ U;  out = scatter(y) * (1/3) + x
// fp16 mma.sync GEMM, warp tile 64x64, CTA 128x256; y stored fp16.
// ===========================================================================

namespace {
constexpr int M = 8 * 2048;   // 16384
constexpr int C = 1024;
constexpr float RAND_SCALE = 1.0f / 3.0f;

constexpr int BM = 128, BN = 256, BK = 64;
constexpr int NKT = C / BK;                  // 16 k-tiles
constexpr int STAGES = 3;
constexpr int A_SM_BYTES = BM * BK * 2;      // 16384 (row = 128 B, 8 x 16B chunks)
constexpr int B_SM_BYTES = BK * BN * 2;      // 32768 (row = 512 B, 32 x 16B chunks)
constexpr int STAGE_BYTES = A_SM_BYTES + B_SM_BYTES;   // 49152
constexpr int GSMEM = STAGES * STAGE_BYTES;            // 147456
}

// Scratch (__device__ globals: allocation-free rule)
__device__ __half g_xg[(size_t)M * C];   // gathered x, fp16 (32 MB)
__device__ __half g_uh[(size_t)C * C];   // U, fp16            (2 MB)
__device__ __half g_y [(size_t)M * C];   // y = xg @ U, fp16  (32 MB)

// ---------------------------------------------------------------------------
__device__ __forceinline__ void cp_async16(uint32_t dst, const void* src) {
    asm volatile("cp.async.cg.shared.global [%0], [%1], 16;" :: "r"(dst), "l"(src));
}
__device__ __forceinline__ uint32_t smem_u32(const void* p) {
    uint32_t a;
    asm("{ .reg .u64 t; cvta.to.shared.u64 t, %1; cvt.u32.u64 %0, t; }" : "=r"(a) : "l"(p));
    return a;
}
__device__ __forceinline__ void ldsm_x4(uint32_t r[4], uint32_t addr) {
    asm volatile("ldmatrix.sync.aligned.m8n8.x4.shared.b16 {%0,%1,%2,%3}, [%4];"
                 : "=r"(r[0]), "=r"(r[1]), "=r"(r[2]), "=r"(r[3]) : "r"(addr));
}
__device__ __forceinline__ void ldsm_x4_t(uint32_t r[4], uint32_t addr) {
    asm volatile("ldmatrix.sync.aligned.m8n8.x4.trans.shared.b16 {%0,%1,%2,%3}, [%4];"
                 : "=r"(r[0]), "=r"(r[1]), "=r"(r[2]), "=r"(r[3]) : "r"(addr));
}
__device__ __forceinline__ void mma_f16(float c[4], const uint32_t a[4], uint32_t b0, uint32_t b1) {
    asm volatile(
        "mma.sync.aligned.m16n8k16.row.col.f32.f16.f16.f32 "
        "{%0,%1,%2,%3}, {%4,%5,%6,%7}, {%8,%9}, {%0,%1,%2,%3};"
        : "+f"(c[0]), "+f"(c[1]), "+f"(c[2]), "+f"(c[3])
        : "r"(a[0]), "r"(a[1]), "r"(a[2]), "r"(a[3]), "r"(b0), "r"(b1));
}

// ---------------------------------------------------------------------------
// Stage 1: per-row gather -> fp16.
// ---------------------------------------------------------------------------
__global__ void __launch_bounds__(256)
gather_kernel(const float* __restrict__ x,
              const int*   __restrict__ perm,
              const int*   __restrict__ randint) {
    __shared__ float sx[4][C];
    const int r0 = blockIdx.x * 4;
    const unsigned mult = ((unsigned)randint[0] * 6u) & 1023u;
    const int tid = threadIdx.x;

    #pragma unroll
    for (int i = 0; i < 4; i++) {
        int id = tid + i * 256;
        int rr = id >> 8, c4 = (id & 255) * 4;
        *reinterpret_cast<float4*>(&sx[rr][c4]) =
            *reinterpret_cast<const float4*>(x + (size_t)(r0 + rr) * C + c4);
    }
    __syncthreads();

    #pragma unroll
    for (int i = 0; i < 8; i++) {
        int id = tid + i * 256;
        int rr = id >> 9, j = (id & 511) * 2;
        unsigned m = (mult * (unsigned)(r0 + rr) + 1u) & 1023u;
        unsigned a0 = ((unsigned)perm[j]     * m) & 1023u;
        unsigned a1 = ((unsigned)perm[j + 1] * m) & 1023u;
        __half2 h = __floats2half2_rn(sx[rr][a0], sx[rr][a1]);
        *reinterpret_cast<__half2*>(g_xg + (size_t)(r0 + rr) * C + j) = h;
    }
}

// ---------------------------------------------------------------------------
// Stage 1b: g_uh = f16(U)
// ---------------------------------------------------------------------------
__global__ void __launch_bounds__(256)
uconv_kernel(const float* __restrict__ U) {
    int i = (blockIdx.x * 256 + threadIdx.x) * 4;
    float4 v = *reinterpret_cast<const float4*>(U + i);
    *reinterpret_cast<__half2*>(g_uh + i)     = __floats2half2_rn(v.x, v.y);
    *reinterpret_cast<__half2*>(g_uh + i + 2) = __floats2half2_rn(v.z, v.w);
}

// ---------------------------------------------------------------------------
// Stage 2: y = xg @ U, fp16 mma m16n8k16, fp32 accum.
// CTA 128x256x64, 256 thr, warps 2(m)x4(n), warp tile 64x64.
// ---------------------------------------------------------------------------
__device__ __forceinline__ void fill_stage(int f, int tid, uint32_t smb, int by, int bx) {
    const int s = f % STAGES;
    const uint32_t a_base = smb + s * STAGE_BYTES;
    const uint32_t b_base = a_base + A_SM_BYTES;
    const __half* Ag = g_xg + (size_t)(by * BM) * C + f * BK;
    const __half* Bg = g_uh + (size_t)(f * BK) * C + bx * BN;
    #pragma unroll
    for (int i = 0; i < 4; i++) {               // A: 128 rows x 8 chunks
        int id = tid + i * 256;
        int r = id >> 3, c = id & 7;
        cp_async16(a_base + r * 128 + ((c ^ (r & 7)) << 4), Ag + (size_t)r * C + c * 8);
    }
    #pragma unroll
    for (int i = 0; i < 8; i++) {               // B: 64 rows x 32 chunks
        int id = tid + i * 256;
        int r = id >> 5, c = id & 31;
        cp_async16(b_base + r * 512 + ((c ^ (r & 7)) << 4), Bg + (size_t)r * C + c * 8);
    }
    asm volatile("cp.async.commit_group;" ::: "memory");
}

__global__ void __launch_bounds__(256, 1)
gemm_kernel() {
    extern __shared__ char smem[];
    const uint32_t smb = smem_u32(smem);

    const int bx  = blockIdx.x;       // 0..3
    const int by  = blockIdx.y;       // 0..127
    const int tid = threadIdx.x;
    const int wid = tid >> 5, lane = tid & 31;
    const int wm  = wid & 1;          // 0..1
    const int wn  = wid >> 1;         // 0..3
    const int l7   = lane & 7;
    const int seg1 = (lane >> 3) & 1;
    const int seg2 = lane >> 4;

    float acc[4][8][4];               // [mt][nt][frag] = 128 regs
    #pragma unroll
    for (int i = 0; i < 4; i++)
        #pragma unroll
        for (int j = 0; j < 8; j++)
            #pragma unroll
            for (int q = 0; q < 4; q++) acc[i][j][q] = 0.f;

    #pragma unroll
    for (int f = 0; f < STAGES - 1; f++) fill_stage(f, tid, smb, by, bx);

    const int a_rowloc = wm * 64 + l7 + seg1 * 8;   // + mt*16
    const int b_kloc   = l7 + seg1 * 8;             // + ks*16
    const int b_ccbase = wn * 8 + seg2;             // + nb*2 (16B-chunk idx)

    for (int kt = 0; kt < NKT; kt++) {
        asm volatile("cp.async.wait_group %0;" :: "n"(STAGES - 2) : "memory");
        __syncthreads();

        const int f = kt + STAGES - 1;
        if (f < NKT) fill_stage(f, tid, smb, by, bx);

        const int s = kt % STAGES;
        const uint32_t As = smb + s * STAGE_BYTES;
        const uint32_t Bs = As + A_SM_BYTES;

        #pragma unroll
        for (int ks = 0; ks < 4; ks++) {
            uint32_t afr[4][4], bfr[4][4];
            const int a_chunk = 2 * ks + seg2;
            #pragma unroll
            for (int mt = 0; mt < 4; mt++)
                ldsm_x4(afr[mt], As + (a_rowloc + mt * 16) * 128 + ((a_chunk ^ l7) << 4));
            const int bk = ks * 16 + b_kloc;
            #pragma unroll
            for (int nb = 0; nb < 4; nb++)
                ldsm_x4_t(bfr[nb], Bs + bk * 512 + (((b_ccbase + nb * 2) ^ l7) << 4));
            #pragma unroll
            for (int mt = 0; mt < 4; mt++)
                #pragma unroll
                for (int nt = 0; nt < 8; nt++)
                    mma_f16(acc[mt][nt], afr[mt],
                            bfr[nt >> 1][2 * (nt & 1)], bfr[nt >> 1][2 * (nt & 1) + 1]);
        }
        __syncthreads();
    }

    // Epilogue -> fp16 y.  c0,c1 @ (g,2t), c2,c3 @ (g+8,2t)
    const int qid = lane >> 2, tq = lane & 3;
    #pragma unroll
    for (int mt = 0; mt < 4; mt++) {
        const int row = by * BM + wm * 64 + mt * 16 + qid;
        #pragma unroll
        for (int nt = 0; nt < 8; nt++) {
            const int col = bx * BN + wn * 64 + nt * 8 + 2 * tq;
            __half* p0 = g_y + (size_t)row * C + col;
            *reinterpret_cast<__half2*>(p0)         = __floats2half2_rn(acc[mt][nt][0], acc[mt][nt][1]);
            *reinterpret_cast<__half2*>(p0 + 8 * C) = __floats2half2_rn(acc[mt][nt][2], acc[mt][nt][3]);
        }
    }
}

// ---------------------------------------------------------------------------
// Stage 3: scatter + residual.  out[r][a(i)] = y[r][i]/3 + x[r][a(i)]
// 8 rows per 512-thread block; y read as fp16.
// ---------------------------------------------------------------------------
__global__ void __launch_bounds__(512)
scatter_kernel(const float* __restrict__ x,
               const int*   __restrict__ perm,
               const int*   __restrict__ randint,
               float*       __restrict__ out) {
    __shared__ float so[8][C];
    const int r0 = blockIdx.x * 8;
    const unsigned mult = ((unsigned)randint[0] * 6u) & 1023u;
    const int tid = threadIdx.x;

    // Phase 1: linear read of fp16 y, scattered store into smem
    #pragma unroll
    for (int i = 0; i < 8; i++) {
        int id = tid + i * 512;                  // 0..4095 half2 chunks
        int rr = id >> 9, j = (id & 511) * 2;
        unsigned m = (mult * (unsigned)(r0 + rr) + 1u) & 1023u;
        float2 v = __half22float2(
            *reinterpret_cast<const __half2*>(g_y + (size_t)(r0 + rr) * C + j));
        so[rr][((unsigned)perm[j]     * m) & 1023u] = v.x;
        so[rr][((unsigned)perm[j + 1] * m) & 1023u] = v.y;
    }
    __syncthreads();

    // Phase 2: coalesced out = so/3 + x
    #pragma unroll
    for (int i = 0; i < 4; i++) {
        int id = tid + i * 512;
        int rr = id >> 8, j = (id & 255) * 4;
        const size_t off = (size_t)(r0 + rr) * C + j;
        float4 xv = *reinterpret_cast<const float4*>(x + off);
        float4 o;
        o.x = fmaf(so[rr][j],     RAND_SCALE, xv.x);
        o.y = fmaf(so[rr][j + 1], RAND_SCALE, xv.y);
        o.z = fmaf(so[rr][j + 2], RAND_SCALE, xv.z);
        o.w = fmaf(so[rr][j + 3], RAND_SCALE, xv.w);
        *reinterpret_cast<float4*>(out + off) = o;
    }
}

// ---------------------------------------------------------------------------
extern "C" void kernel_launch(void* const* d_in, const int* in_sizes, int n_in,
                              void* d_out, int out_size) {
    const float* x       = (const float*)d_in[0];
    const float* U       = (const float*)d_in[1];
    const int*   perm    = (const int*)d_in[2];
    const int*   randint = (const int*)d_in[3];
    float*       out     = (float*)d_out;

    static bool attr_done = false;
    if (!attr_done) {
        cudaFuncSetAttribute(gemm_kernel,
                             cudaFuncAttributeMaxDynamicSharedMemorySize, GSMEM);
        attr_done = true;
    }

    gather_kernel<<<M / 4, 256>>>(x, perm, randint);
    uconv_kernel<<<(C * C) / (256 * 4), 256>>>(U);
    gemm_kernel<<<dim3(C / BN, M / BM), 256, GSMEM>>>();
    scatter_kernel<<<M / 8, 512>>>(x, perm, randint, out);
}

// round 6
// speedup vs baseline: 1.1231x; 1.1231x over previous
#include <cuda_runtime.h>
#include <cuda_fp16.h>
#include <cstdint>

// ===========================================================================
// GaussProjDrop: x[16384,1024] f32; per-row perm a_r(i) = (perm[i]*m_r) & 1023,
// m_r = (6*randint*r + 1) & 1023 (odd -> bijection since n = 2^10).
//   y = gather(x) @ U;  out = scatter(y) * (1/3) + x
// fp16 mma.sync GEMM (R4 config: 128x128x64, warp 64x32, 2 CTA/SM), y fp16.
// ===========================================================================

namespace {
constexpr int M = 8 * 2048;   // 16384
constexpr int C = 1024;
constexpr float RAND_SCALE = 1.0f / 3.0f;

constexpr int BM = 128, BN = 128, BK = 64;
constexpr int NKT = C / BK;                  // 16 k-tiles
constexpr int STAGES = 3;
constexpr int A_SM_BYTES = BM * BK * 2;      // 16384 (row = 128 B, 8 x 16B chunks)
constexpr int B_SM_BYTES = BK * BN * 2;      // 16384 (row = 256 B, 16 x 16B chunks)
constexpr int STAGE_BYTES = A_SM_BYTES + B_SM_BYTES;   // 32768
constexpr int GSMEM = STAGES * STAGE_BYTES;            // 98304 -> 2 CTA/SM
}

// Scratch (__device__ globals: allocation-free rule)
__device__ __half g_xg[(size_t)M * C];   // gathered x, fp16 (32 MB)
__device__ __half g_uh[(size_t)C * C];   // U, fp16            (2 MB)
__device__ __half g_y [(size_t)M * C];   // y = xg @ U, fp16  (32 MB)

// ---------------------------------------------------------------------------
__device__ __forceinline__ void cp_async16(uint32_t dst, const void* src) {
    asm volatile("cp.async.cg.shared.global [%0], [%1], 16;" :: "r"(dst), "l"(src));
}
__device__ __forceinline__ uint32_t smem_u32(const void* p) {
    uint32_t a;
    asm("{ .reg .u64 t; cvta.to.shared.u64 t, %1; cvt.u32.u64 %0, t; }" : "=r"(a) : "l"(p));
    return a;
}
__device__ __forceinline__ void ldsm_x4(uint32_t r[4], uint32_t addr) {
    asm volatile("ldmatrix.sync.aligned.m8n8.x4.shared.b16 {%0,%1,%2,%3}, [%4];"
                 : "=r"(r[0]), "=r"(r[1]), "=r"(r[2]), "=r"(r[3]) : "r"(addr));
}
__device__ __forceinline__ void ldsm_x4_t(uint32_t r[4], uint32_t addr) {
    asm volatile("ldmatrix.sync.aligned.m8n8.x4.trans.shared.b16 {%0,%1,%2,%3}, [%4];"
                 : "=r"(r[0]), "=r"(r[1]), "=r"(r[2]), "=r"(r[3]) : "r"(addr));
}
__device__ __forceinline__ void mma_f16(float c[4], const uint32_t a[4], uint32_t b0, uint32_t b1) {
    asm volatile(
        "mma.sync.aligned.m16n8k16.row.col.f32.f16.f16.f32 "
        "{%0,%1,%2,%3}, {%4,%5,%6,%7}, {%8,%9}, {%0,%1,%2,%3};"
        : "+f"(c[0]), "+f"(c[1]), "+f"(c[2]), "+f"(c[3])
        : "r"(a[0]), "r"(a[1]), "r"(a[2]), "r"(a[3]), "r"(b0), "r"(b1));
}

// ---------------------------------------------------------------------------
// Stage 1: per-row gather -> fp16.
// ---------------------------------------------------------------------------
__global__ void __launch_bounds__(256)
gather_kernel(const float* __restrict__ x,
              const int*   __restrict__ perm,
              const int*   __restrict__ randint) {
    __shared__ float sx[4][C];
    const int r0 = blockIdx.x * 4;
    const unsigned mult = ((unsigned)randint[0] * 6u) & 1023u;
    const int tid = threadIdx.x;

    #pragma unroll
    for (int i = 0; i < 4; i++) {
        int id = tid + i * 256;
        int rr = id >> 8, c4 = (id & 255) * 4;
        *reinterpret_cast<float4*>(&sx[rr][c4]) =
            *reinterpret_cast<const float4*>(x + (size_t)(r0 + rr) * C + c4);
    }
    __syncthreads();

    #pragma unroll
    for (int i = 0; i < 8; i++) {
        int id = tid + i * 256;
        int rr = id >> 9, j = (id & 511) * 2;
        unsigned m = (mult * (unsigned)(r0 + rr) + 1u) & 1023u;
        unsigned a0 = ((unsigned)perm[j]     * m) & 1023u;
        unsigned a1 = ((unsigned)perm[j + 1] * m) & 1023u;
        __half2 h = __floats2half2_rn(sx[rr][a0], sx[rr][a1]);
        *reinterpret_cast<__half2*>(g_xg + (size_t)(r0 + rr) * C + j) = h;
    }
}

// ---------------------------------------------------------------------------
// Stage 1b: g_uh = f16(U)
// ---------------------------------------------------------------------------
__global__ void __launch_bounds__(256)
uconv_kernel(const float* __restrict__ U) {
    int i = (blockIdx.x * 256 + threadIdx.x) * 4;
    float4 v = *reinterpret_cast<const float4*>(U + i);
    *reinterpret_cast<__half2*>(g_uh + i)     = __floats2half2_rn(v.x, v.y);
    *reinterpret_cast<__half2*>(g_uh + i + 2) = __floats2half2_rn(v.z, v.w);
}

// ---------------------------------------------------------------------------
// Stage 2: y = xg @ U, fp16 mma m16n8k16, fp32 accum.
// CTA 128x128x64, 256 thr, warps 2(m)x4(n), warp tile 64x32.  2 CTA/SM.
// ---------------------------------------------------------------------------
__device__ __forceinline__ void fill_stage(int f, int tid, uint32_t smb, int by, int bx) {
    const int s = f % STAGES;
    const uint32_t a_base = smb + s * STAGE_BYTES;
    const uint32_t b_base = a_base + A_SM_BYTES;
    const __half* Ag = g_xg + (size_t)(by * BM) * C + f * BK;
    const __half* Bg = g_uh + (size_t)(f * BK) * C + bx * BN;
    #pragma unroll
    for (int i = 0; i < 4; i++) {               // A: 128 rows x 8 chunks
        int id = tid + i * 256;
        int r = id >> 3, c = id & 7;
        cp_async16(a_base + r * 128 + ((c ^ (r & 7)) << 4), Ag + (size_t)r * C + c * 8);
    }
    #pragma unroll
    for (int i = 0; i < 4; i++) {               // B: 64 rows x 16 chunks
        int id = tid + i * 256;
        int r = id >> 4, c = id & 15;
        cp_async16(b_base + r * 256 + ((c ^ (r & 7)) << 4), Bg + (size_t)r * C + c * 8);
    }
    asm volatile("cp.async.commit_group;" ::: "memory");
}

__global__ void __launch_bounds__(256, 2)
gemm_kernel() {
    extern __shared__ char smem[];
    const uint32_t smb = smem_u32(smem);

    const int bx  = blockIdx.x;       // 0..7
    const int by  = blockIdx.y;       // 0..127
    const int tid = threadIdx.x;
    const int wid = tid >> 5, lane = tid & 31;
    const int wm  = wid & 1;          // 0..1
    const int wn  = wid >> 1;         // 0..3
    const int l7   = lane & 7;
    const int seg1 = (lane >> 3) & 1;
    const int seg2 = lane >> 4;

    float acc[4][4][4];
    #pragma unroll
    for (int i = 0; i < 4; i++)
        #pragma unroll
        for (int j = 0; j < 4; j++)
            #pragma unroll
            for (int q = 0; q < 4; q++) acc[i][j][q] = 0.f;

    #pragma unroll
    for (int f = 0; f < STAGES - 1; f++) fill_stage(f, tid, smb, by, bx);

    const int a_rowloc = wm * 64 + l7 + seg1 * 8;   // + mt*16
    const int b_kloc   = l7 + seg1 * 8;             // + ks*16
    const int b_ccbase = wn * 4 + seg2;             // + nb*2 (16B-chunk idx)

    for (int kt = 0; kt < NKT; kt++) {
        asm volatile("cp.async.wait_group %0;" :: "n"(STAGES - 2) : "memory");
        __syncthreads();

        const int f = kt + STAGES - 1;
        if (f < NKT) fill_stage(f, tid, smb, by, bx);

        const int s = kt % STAGES;
        const uint32_t As = smb + s * STAGE_BYTES;
        const uint32_t Bs = As + A_SM_BYTES;

        #pragma unroll
        for (int ks = 0; ks < 4; ks++) {
            uint32_t afr[4][4], bfr[2][4];
            const int a_chunk = 2 * ks + seg2;
            #pragma unroll
            for (int mt = 0; mt < 4; mt++)
                ldsm_x4(afr[mt], As + (a_rowloc + mt * 16) * 128 + ((a_chunk ^ l7) << 4));
            const int bk = ks * 16 + b_kloc;
            #pragma unroll
            for (int nb = 0; nb < 2; nb++)
                ldsm_x4_t(bfr[nb], Bs + bk * 256 + (((b_ccbase + nb * 2) ^ l7) << 4));
            #pragma unroll
            for (int mt = 0; mt < 4; mt++)
                #pragma unroll
                for (int nt = 0; nt < 4; nt++)
                    mma_f16(acc[mt][nt], afr[mt],
                            bfr[nt >> 1][2 * (nt & 1)], bfr[nt >> 1][2 * (nt & 1) + 1]);
        }
        __syncthreads();
    }

    // Epilogue -> fp16 y.  c0,c1 @ (g,2t), c2,c3 @ (g+8,2t)
    const int qid = lane >> 2, tq = lane & 3;
    #pragma unroll
    for (int mt = 0; mt < 4; mt++) {
        const int row = by * BM + wm * 64 + mt * 16 + qid;
        #pragma unroll
        for (int nt = 0; nt < 4; nt++) {
            const int col = bx * BN + wn * 32 + nt * 8 + 2 * tq;
            __half* p0 = g_y + (size_t)row * C + col;
            *reinterpret_cast<__half2*>(p0)         = __floats2half2_rn(acc[mt][nt][0], acc[mt][nt][1]);
            *reinterpret_cast<__half2*>(p0 + 8 * C) = __floats2half2_rn(acc[mt][nt][2], acc[mt][nt][3]);
        }
    }
}

// ---------------------------------------------------------------------------
// Stage 3: scatter + residual.  out[r][a(i)] = y[r][i]/3 + x[r][a(i)]
// 8 rows per 512-thread block; y read as fp16.
// ---------------------------------------------------------------------------
__global__ void __launch_bounds__(512)
scatter_kernel(const float* __restrict__ x,
               const int*   __restrict__ perm,
               const int*   __restrict__ randint,
               float*       __restrict__ out) {
    __shared__ float so[8][C];
    const int r0 = blockIdx.x * 8;
    const unsigned mult = ((unsigned)randint[0] * 6u) & 1023u;
    const int tid = threadIdx.x;

    // Phase 1: linear read of fp16 y, scattered store into smem
    #pragma unroll
    for (int i = 0; i < 8; i++) {
        int id = tid + i * 512;                  // 0..4095 half2 chunks
        int rr = id >> 9, j = (id & 511) * 2;
        unsigned m = (mult * (unsigned)(r0 + rr) + 1u) & 1023u;
        float2 v = __half22float2(
            *reinterpret_cast<const __half2*>(g_y + (size_t)(r0 + rr) * C + j));
        so[rr][((unsigned)perm[j]     * m) & 1023u] = v.x;
        so[rr][((unsigned)perm[j + 1] * m) & 1023u] = v.y;
    }
    __syncthreads();

    // Phase 2: coalesced out = so/3 + x
    #pragma unroll
    for (int i = 0; i < 4; i++) {
        int id = tid + i * 512;
        int rr = id >> 8, j = (id & 255) * 4;
        const size_t off = (size_t)(r0 + rr) * C + j;
        float4 xv = *reinterpret_cast<const float4*>(x + off);
        float4 o;
        o.x = fmaf(so[rr][j],     RAND_SCALE, xv.x);
        o.y = fmaf(so[rr][j + 1], RAND_SCALE, xv.y);
        o.z = fmaf(so[rr][j + 2], RAND_SCALE, xv.z);
        o.w = fmaf(so[rr][j + 3], RAND_SCALE, xv.w);
        *reinterpret_cast<float4*>(out + off) = o;
    }
}

// ---------------------------------------------------------------------------
extern "C" void kernel_launch(void* const* d_in, const int* in_sizes, int n_in,
                              void* d_out, int out_size) {
    const float* x       = (const float*)d_in[0];
    const float* U       = (const float*)d_in[1];
    const int*   perm    = (const int*)d_in[2];
    const int*   randint = (const int*)d_in[3];
    float*       out     = (float*)d_out;

    static bool attr_done = false;
    if (!attr_done) {
        cudaFuncSetAttribute(gemm_kernel,
                             cudaFuncAttributeMaxDynamicSharedMemorySize, GSMEM);
        attr_done = true;
    }

    gather_kernel<<<M / 4, 256>>>(x, perm, randint);
    uconv_kernel<<<(C * C) / (256 * 4), 256>>>(U);
    gemm_kernel<<<dim3(C / BN, M / BM), 256, GSMEM>>>();
    scatter_kernel<<<M / 8, 512>>>(x, perm, randint, out);
}

// round 7
// speedup vs baseline: 1.1403x; 1.0153x over previous
#include <cuda_runtime.h>
#include <cuda_fp16.h>
#include <cstdint>

// ===========================================================================
// GaussProjDrop: x[16384,1024] f32; per-row perm a_r(i) = (perm[i]*m_r) & 1023,
// m_r = (6*randint*r + 1) & 1023 (odd -> bijection since n = 2^10).
//   y = gather(x) @ U;  out = scatter(y) * (1/3) + x
// fp16 mma.sync GEMM (128x128x64, warp 64x32, 2 CTA/SM), y fp16.
// R7: single-barrier GEMM mainloop; uconv merged into gather launch.
// ===========================================================================

namespace {
constexpr int M = 8 * 2048;   // 16384
constexpr int C = 1024;
constexpr float RAND_SCALE = 1.0f / 3.0f;

constexpr int BM = 128, BN = 128, BK = 64;
constexpr int NKT = C / BK;                  // 16 k-tiles
constexpr int STAGES = 3;
constexpr int A_SM_BYTES = BM * BK * 2;      // 16384
constexpr int B_SM_BYTES = BK * BN * 2;      // 16384
constexpr int STAGE_BYTES = A_SM_BYTES + B_SM_BYTES;   // 32768
constexpr int GSMEM = STAGES * STAGE_BYTES;            // 98304 -> 2 CTA/SM

constexpr int GATHER_BLOCKS = M / 4;         // 4096
constexpr int UCONV_BLOCKS  = (C * C) / (256 * 4);  // 1024
}

// Scratch (__device__ globals: allocation-free rule)
__device__ __half g_xg[(size_t)M * C];   // gathered x, fp16 (32 MB)
__device__ __half g_uh[(size_t)C * C];   // U, fp16            (2 MB)
__device__ __half g_y [(size_t)M * C];   // y = xg @ U, fp16  (32 MB)

// ---------------------------------------------------------------------------
__device__ __forceinline__ void cp_async16(uint32_t dst, const void* src) {
    asm volatile("cp.async.cg.shared.global [%0], [%1], 16;" :: "r"(dst), "l"(src));
}
__device__ __forceinline__ uint32_t smem_u32(const void* p) {
    uint32_t a;
    asm("{ .reg .u64 t; cvta.to.shared.u64 t, %1; cvt.u32.u64 %0, t; }" : "=r"(a) : "l"(p));
    return a;
}
__device__ __forceinline__ void ldsm_x4(uint32_t r[4], uint32_t addr) {
    asm volatile("ldmatrix.sync.aligned.m8n8.x4.shared.b16 {%0,%1,%2,%3}, [%4];"
                 : "=r"(r[0]), "=r"(r[1]), "=r"(r[2]), "=r"(r[3]) : "r"(addr));
}
__device__ __forceinline__ void ldsm_x4_t(uint32_t r[4], uint32_t addr) {
    asm volatile("ldmatrix.sync.aligned.m8n8.x4.trans.shared.b16 {%0,%1,%2,%3}, [%4];"
                 : "=r"(r[0]), "=r"(r[1]), "=r"(r[2]), "=r"(r[3]) : "r"(addr));
}
__device__ __forceinline__ void mma_f16(float c[4], const uint32_t a[4], uint32_t b0, uint32_t b1) {
    asm volatile(
        "mma.sync.aligned.m16n8k16.row.col.f32.f16.f16.f32 "
        "{%0,%1,%2,%3}, {%4,%5,%6,%7}, {%8,%9}, {%0,%1,%2,%3};"
        : "+f"(c[0]), "+f"(c[1]), "+f"(c[2]), "+f"(c[3])
        : "r"(a[0]), "r"(a[1]), "r"(a[2]), "r"(a[3]), "r"(b0), "r"(b1));
}

// ---------------------------------------------------------------------------
// Stage 1 (merged): blocks [0, M/4) do the per-row gather -> fp16;
// blocks [M/4, M/4 + 1024) convert U -> fp16.
// ---------------------------------------------------------------------------
__global__ void __launch_bounds__(256)
gather_uconv_kernel(const float* __restrict__ x,
                    const float* __restrict__ U,
                    const int*   __restrict__ perm,
                    const int*   __restrict__ randint) {
    const int tid = threadIdx.x;

    if (blockIdx.x >= GATHER_BLOCKS) {
        // ---- uconv part: g_uh = f16(U) ----
        int i = ((blockIdx.x - GATHER_BLOCKS) * 256 + tid) * 4;
        float4 v = *reinterpret_cast<const float4*>(U + i);
        *reinterpret_cast<__half2*>(g_uh + i)     = __floats2half2_rn(v.x, v.y);
        *reinterpret_cast<__half2*>(g_uh + i + 2) = __floats2half2_rn(v.z, v.w);
        return;
    }

    // ---- gather part ----
    __shared__ float sx[4][C];
    const int r0 = blockIdx.x * 4;
    const unsigned mult = ((unsigned)randint[0] * 6u) & 1023u;

    #pragma unroll
    for (int i = 0; i < 4; i++) {
        int id = tid + i * 256;
        int rr = id >> 8, c4 = (id & 255) * 4;
        *reinterpret_cast<float4*>(&sx[rr][c4]) =
            *reinterpret_cast<const float4*>(x + (size_t)(r0 + rr) * C + c4);
    }
    __syncthreads();

    #pragma unroll
    for (int i = 0; i < 8; i++) {
        int id = tid + i * 256;
        int rr = id >> 9, j = (id & 511) * 2;
        unsigned m = (mult * (unsigned)(r0 + rr) + 1u) & 1023u;
        unsigned a0 = ((unsigned)perm[j]     * m) & 1023u;
        unsigned a1 = ((unsigned)perm[j + 1] * m) & 1023u;
        __half2 h = __floats2half2_rn(sx[rr][a0], sx[rr][a1]);
        *reinterpret_cast<__half2*>(g_xg + (size_t)(r0 + rr) * C + j) = h;
    }
}

// ---------------------------------------------------------------------------
// Stage 2: y = xg @ U, fp16 mma m16n8k16, fp32 accum.
// CTA 128x128x64, 256 thr, warps 2(m)x4(n), warp tile 64x32.  2 CTA/SM.
// Single __syncthreads per k-iteration (trailing barrier proven redundant).
// ---------------------------------------------------------------------------
__device__ __forceinline__ void fill_stage(int f, int tid, uint32_t smb, int by, int bx) {
    const int s = f % STAGES;
    const uint32_t a_base = smb + s * STAGE_BYTES;
    const uint32_t b_base = a_base + A_SM_BYTES;
    const __half* Ag = g_xg + (size_t)(by * BM) * C + f * BK;
    const __half* Bg = g_uh + (size_t)(f * BK) * C + bx * BN;
    #pragma unroll
    for (int i = 0; i < 4; i++) {               // A: 128 rows x 8 chunks
        int id = tid + i * 256;
        int r = id >> 3, c = id & 7;
        cp_async16(a_base + r * 128 + ((c ^ (r & 7)) << 4), Ag + (size_t)r * C + c * 8);
    }
    #pragma unroll
    for (int i = 0; i < 4; i++) {               // B: 64 rows x 16 chunks
        int id = tid + i * 256;
        int r = id >> 4, c = id & 15;
        cp_async16(b_base + r * 256 + ((c ^ (r & 7)) << 4), Bg + (size_t)r * C + c * 8);
    }
    asm volatile("cp.async.commit_group;" ::: "memory");
}

__global__ void __launch_bounds__(256, 2)
gemm_kernel() {
    extern __shared__ char smem[];
    const uint32_t smb = smem_u32(smem);

    const int bx  = blockIdx.x;       // 0..7
    const int by  = blockIdx.y;       // 0..127
    const int tid = threadIdx.x;
    const int wid = tid >> 5, lane = tid & 31;
    const int wm  = wid & 1;          // 0..1
    const int wn  = wid >> 1;         // 0..3
    const int l7   = lane & 7;
    const int seg1 = (lane >> 3) & 1;
    const int seg2 = lane >> 4;

    float acc[4][4][4];
    #pragma unroll
    for (int i = 0; i < 4; i++)
        #pragma unroll
        for (int j = 0; j < 4; j++)
            #pragma unroll
            for (int q = 0; q < 4; q++) acc[i][j][q] = 0.f;

    #pragma unroll
    for (int f = 0; f < STAGES - 1; f++) fill_stage(f, tid, smb, by, bx);

    const int a_rowloc = wm * 64 + l7 + seg1 * 8;   // + mt*16
    const int b_kloc   = l7 + seg1 * 8;             // + ks*16
    const int b_ccbase = wn * 4 + seg2;             // + nb*2 (16B-chunk idx)

    for (int kt = 0; kt < NKT; kt++) {
        asm volatile("cp.async.wait_group %0;" :: "n"(STAGES - 2) : "memory");
        __syncthreads();
        // Barrier proof: fill(kt+2) below writes slot (kt+2)%3 == (kt-1)%3,
        // whose readers (compute of iter kt-1) all passed the barrier above.

        const int f = kt + STAGES - 1;
        if (f < NKT) fill_stage(f, tid, smb, by, bx);

        const int s = kt % STAGES;
        const uint32_t As = smb + s * STAGE_BYTES;
        const uint32_t Bs = As + A_SM_BYTES;

        #pragma unroll
        for (int ks = 0; ks < 4; ks++) {
            uint32_t afr[4][4], bfr[2][4];
            const int a_chunk = 2 * ks + seg2;
            #pragma unroll
            for (int mt = 0; mt < 4; mt++)
                ldsm_x4(afr[mt], As + (a_rowloc + mt * 16) * 128 + ((a_chunk ^ l7) << 4));
            const int bk = ks * 16 + b_kloc;
            #pragma unroll
            for (int nb = 0; nb < 2; nb++)
                ldsm_x4_t(bfr[nb], Bs + bk * 256 + (((b_ccbase + nb * 2) ^ l7) << 4));
            #pragma unroll
            for (int mt = 0; mt < 4; mt++)
                #pragma unroll
                for (int nt = 0; nt < 4; nt++)
                    mma_f16(acc[mt][nt], afr[mt],
                            bfr[nt >> 1][2 * (nt & 1)], bfr[nt >> 1][2 * (nt & 1) + 1]);
        }
    }

    // Epilogue -> fp16 y.  c0,c1 @ (g,2t), c2,c3 @ (g+8,2t)
    const int qid = lane >> 2, tq = lane & 3;
    #pragma unroll
    for (int mt = 0; mt < 4; mt++) {
        const int row = by * BM + wm * 64 + mt * 16 + qid;
        #pragma unroll
        for (int nt = 0; nt < 4; nt++) {
            const int col = bx * BN + wn * 32 + nt * 8 + 2 * tq;
            __half* p0 = g_y + (size_t)row * C + col;
            *reinterpret_cast<__half2*>(p0)         = __floats2half2_rn(acc[mt][nt][0], acc[mt][nt][1]);
            *reinterpret_cast<__half2*>(p0 + 8 * C) = __floats2half2_rn(acc[mt][nt][2], acc[mt][nt][3]);
        }
    }
}

// ---------------------------------------------------------------------------
// Stage 3: scatter + residual.  out[r][a(i)] = y[r][i]/3 + x[r][a(i)]
// 8 rows per 512-thread block; y read as fp16.
// ---------------------------------------------------------------------------
__global__ void __launch_bounds__(512)
scatter_kernel(const float* __restrict__ x,
               const int*   __restrict__ perm,
               const int*   __restrict__ randint,
               float*       __restrict__ out) {
    __shared__ float so[8][C];
    const int r0 = blockIdx.x * 8;
    const unsigned mult = ((unsigned)randint[0] * 6u) & 1023u;
    const int tid = threadIdx.x;

    // Phase 1: linear read of fp16 y, scattered store into smem
    #pragma unroll
    for (int i = 0; i < 8; i++) {
        int id = tid + i * 512;                  // 0..4095 half2 chunks
        int rr = id >> 9, j = (id & 511) * 2;
        unsigned m = (mult * (unsigned)(r0 + rr) + 1u) & 1023u;
        float2 v = __half22float2(
            *reinterpret_cast<const __half2*>(g_y + (size_t)(r0 + rr) * C + j));
        so[rr][((unsigned)perm[j]     * m) & 1023u] = v.x;
        so[rr][((unsigned)perm[j + 1] * m) & 1023u] = v.y;
    }
    __syncthreads();

    // Phase 2: coalesced out = so/3 + x
    #pragma unroll
    for (int i = 0; i < 4; i++) {
        int id = tid + i * 512;
        int rr = id >> 8, j = (id & 255) * 4;
        const size_t off = (size_t)(r0 + rr) * C + j;
        float4 xv = *reinterpret_cast<const float4*>(x + off);
        float4 o;
        o.x = fmaf(so[rr][j],     RAND_SCALE, xv.x);
        o.y = fmaf(so[rr][j + 1], RAND_SCALE, xv.y);
        o.z = fmaf(so[rr][j + 2], RAND_SCALE, xv.z);
        o.w = fmaf(so[rr][j + 3], RAND_SCALE, xv.w);
        *reinterpret_cast<float4*>(out + off) = o;
    }
}

// ---------------------------------------------------------------------------
extern "C" void kernel_launch(void* const* d_in, const int* in_sizes, int n_in,
                              void* d_out, int out_size) {
    const float* x       = (const float*)d_in[0];
    const float* U       = (const float*)d_in[1];
    const int*   perm    = (const int*)d_in[2];
    const int*   randint = (const int*)d_in[3];
    float*       out     = (float*)d_out;

    static bool attr_done = false;
    if (!attr_done) {
        cudaFuncSetAttribute(gemm_kernel,
                             cudaFuncAttributeMaxDynamicSharedMemorySize, GSMEM);
        attr_done = true;
    }

    gather_uconv_kernel<<<GATHER_BLOCKS + UCONV_BLOCKS, 256>>>(x, U, perm, randint);
    gemm_kernel<<<dim3(C / BN, M / BM), 256, GSMEM>>>();
    scatter_kernel<<<M / 8, 512>>>(x, perm, randint, out);
}